// round 14
// baseline (speedup 1.0000x reference)
#include <cuda_runtime.h>
#include <math.h>

#define SEQL 512
#define BATCH 64
#define INF 512
#define HID 1024
#define OUTF 512
#define NBLK 128
#define SCAN_THREADS 512

typedef unsigned long long u64;

// Scratch (device globals; allocation-free)
__device__ float g_xi [(size_t)SEQL * BATCH * HID];   // [t][b][c] row-major
__device__ float g_hsT[(size_t)SEQL * BATCH * HID];   // [t][c][r] transposed
__device__ float g_h0T[(size_t)BATCH * HID];          // [c][r]
__device__ unsigned g_cnt4[128];                      // 4 counters, 32-word spaced

// ---------------- f32x2 helpers ----------------
__device__ __forceinline__ u64 pack2(float x, float y) {
    u64 d; asm("mov.b64 %0,{%1,%2};" : "=l"(d) : "f"(x), "f"(y)); return d;
}
__device__ __forceinline__ float2 unpack2(u64 d) {
    float2 v; asm("mov.b64 {%0,%1},%2;" : "=f"(v.x), "=f"(v.y) : "l"(d)); return v;
}
__device__ __forceinline__ u64 fma2(u64 a, u64 b, u64 c) {
    u64 d; asm("fma.rn.f32x2 %0,%1,%2,%3;" : "=l"(d) : "l"(a), "l"(b), "l"(c)); return d;
}
__device__ __forceinline__ u64 add2(u64 a, u64 b) {
    u64 d; asm("add.rn.f32x2 %0,%1,%2;" : "=l"(d) : "l"(a), "l"(b)); return d;
}

// fast tanh: 1 - 2/(e^{2x}+1). 2 MUFU + few FLOPs, rel err ~1e-6.
__device__ __forceinline__ float fast_tanh(float x) {
    float e = __expf(2.0f * x);
    return 1.0f - __fdividef(2.0f, e + 1.0f);
}

// Dummy first launch: keeps the profiler's capture window on rnn_scan (#4).
__global__ void noop_k() {}

// ---------------------------------------------------------------------------
// Persistent scan: h_t = tanh(xi_t + h_{t-1} @ W).
// 128 blocks = 32 colgroups(32 cols) x 4 rowgroups(16 rows); 512 threads.
// h staged via SMEM; GEMM lane tile 4r x 4c: per warp-k exactly 2 LDS
// (1x LDS.128 h row-quad + 1x LDS.128 w col-quad) + 4 pack-MOVs + 8 FMA2.
// W slice [1024][32] floats in SMEM (128KB). 16 warps = 16 k-splits.
// ---------------------------------------------------------------------------
__global__ void __launch_bounds__(SCAN_THREADS, 1) rnn_scan(
    const float* __restrict__ h0T, const float* __restrict__ W,
    const float* __restrict__ xi, float* __restrict__ hsT)
{
    extern __shared__ char smdyn[];
    float*  wSf = (float*)smdyn;                  // [1024][32] float = 128KB
    float*  hS  = (float*)(smdyn + 131072);       // [512 k][16 r] = 32KB
    u64*  sRed  = (u64*)(smdyn + 131072 + 32768); // [16][32][9] u64 = 36864B

    const int tid = threadIdx.x;
    const int cgB = blockIdx.x >> 2;       // colgroup 0..31
    const int rgB = blockIdx.x & 3;        // rowgroup 0..3
    const int cb  = cgB * 32;
    const int rb  = rgB * 16;

    // Load W column slice once: wSf[k*32 + c] = W[k][cb+c]
    for (int i = tid; i < 1024 * 8; i += SCAN_THREADS) {
        int k = i >> 3, c4 = (i & 7) * 4;
        float4 v = *(const float4*)(W + (size_t)k * HID + cb + c4);
        *(float4*)&wSf[k * 32 + c4] = v;
    }

    const int q    = tid >> 5;             // k-split 0..15 (warp id)
    const int l    = tid & 31;
    const int rq   = l & 3;                // row quad 0..3 -> rows rq*4..+4
    const int cq   = l >> 2;               // col quad 0..7 -> cols cq*4..+4

    const int rrc = tid >> 3;              // reduce: local col 0..31
    const int rrp = tid & 7;               // reduce: row pair 0..7

    // staging roles: 4 float4 per thread per phase
    const int st_k0 = tid >> 2;            // base k (0..127), +128 per i
    const int st_rq = (tid & 3) * 4;       // row quad

    unsigned* cnt = &g_cnt4[rgB * 32];     // per-rowgroup barrier counter

    for (int t = 0; t < SEQL; ++t) {
        // ---- prefetch xi for epilogue (hidden under GEMM) ----
        float x0 = 0.f, x1 = 0.f;
        if (tid < 256) {
            const float* xit = xi + (size_t)t * BATCH * HID;
            x0 = __ldg(&xit[(size_t)(rb + 2 * rrp)     * HID + cb + rrc]);
            x1 = __ldg(&xit[(size_t)(rb + 2 * rrp + 1) * HID + cb + rrc]);
        }

        const float* hin = t ? hsT + (size_t)(t - 1) * BATCH * HID : h0T;

        // acc[c*2+rp]: col cq*4+c (c 0..3), rows (rq*4+2rp, rq*4+2rp+1)
        u64 acc[8];
#pragma unroll
        for (int i = 0; i < 8; ++i) acc[i] = 0ull;

        // ---- two phases of 512 k each: stage to SMEM, GEMM from SMEM ----
#pragma unroll
        for (int p = 0; p < 2; ++p) {
            __syncthreads();   // hS free (previous phase/step readers done)
            {
                const float* src = hin + (size_t)(p * 512) * 64 + rb;
#pragma unroll
                for (int i = 0; i < 4; ++i) {
                    int kk = st_k0 + i * 128;
                    float4 v = *(const float4*)(src + (size_t)kk * 64 + st_rq);
                    *(float4*)&hS[kk * 16 + st_rq] = v;
                }
            }
            __syncthreads();

            const float* hp = hS + (q * 32) * 16 + rq * 4;
            const float* wp = wSf + (size_t)(p * 512 + q * 32) * 32 + cq * 4;
#pragma unroll 8
            for (int k = 0; k < 32; ++k) {
                float4 hv4 = *(const float4*)(hp + k * 16);
                float4 w4  = *(const float4*)(wp + k * 32);
                u64 h01 = pack2(hv4.x, hv4.y);
                u64 h23 = pack2(hv4.z, hv4.w);
                u64 w0 = pack2(w4.x, w4.x);
                u64 w1 = pack2(w4.y, w4.y);
                u64 w2 = pack2(w4.z, w4.z);
                u64 w3 = pack2(w4.w, w4.w);
                acc[0] = fma2(h01, w0, acc[0]);
                acc[1] = fma2(h23, w0, acc[1]);
                acc[2] = fma2(h01, w1, acc[2]);
                acc[3] = fma2(h23, w1, acc[3]);
                acc[4] = fma2(h01, w2, acc[4]);
                acc[5] = fma2(h23, w2, acc[5]);
                acc[6] = fma2(h01, w3, acc[6]);
                acc[7] = fma2(h23, w3, acc[7]);
            }
        }

        // ---- partial store: sRed[q][col][rowpair] (rp padded to 9) ----
        {
            u64* base = sRed + (size_t)q * 288;   // 32*9
#pragma unroll
            for (int c = 0; c < 4; ++c)
#pragma unroll
                for (int rp = 0; rp < 2; ++rp)
                    base[(size_t)(cq * 4 + c) * 9 + (rq * 2 + rp)] = acc[c * 2 + rp];
        }
        __syncthreads();

        // ---- 16-way reduce + tanh + store h_t (256 threads, 1 u64 each) ----
        if (tid < 256) {
            u64 s = sRed[(size_t)rrc * 9 + rrp];
#pragma unroll
            for (int qq = 1; qq < 16; ++qq)
                s = add2(s, sRed[(size_t)qq * 288 + (size_t)rrc * 9 + rrp]);
            float2 f = unpack2(s);
            float v0 = fast_tanh(f.x + x0);
            float v1 = fast_tanh(f.y + x1);
            *(u64*)(hsT + (size_t)t * BATCH * HID + (size_t)(cb + rrc) * 64 + rb + 2 * rrp)
                = pack2(v0, v1);
        }

        // ---- rowgroup barrier (32 blocks): release-inc + poll counter ----
        __syncthreads();
        if (tid == 0) {
            asm volatile("red.release.gpu.global.add.u32 [%0], 1;"
                         :: "l"(cnt) : "memory");
        }
        if (tid < 32) {
            const unsigned target = 32u * (unsigned)(t + 1);
            unsigned cur;
            do {
                asm volatile("ld.acquire.gpu.u32 %0,[%1];"
                             : "=r"(cur) : "l"(cnt) : "memory");
            } while (cur < target);
        }
        __syncthreads();
    }
}

// ---------------------------------------------------------------------------
// Double-buffered 128x128x16 f32x2 GEMM: C = A @ B + bias, optional leaky.
// ATRANS: A stored as [M/64][K][64] (transposed hidden-state history).
// ---------------------------------------------------------------------------
template <bool ATRANS, bool LEAKY>
__global__ __launch_bounds__(256) void sgemm_db(
    const float* __restrict__ A, const float* __restrict__ B,
    const float* __restrict__ bias, float* __restrict__ C,
    int M, int N, int K)
{
    constexpr int BM = 128, BN = 128, BK = 16;
    __shared__ __align__(16) float As[2][BK][BM];
    __shared__ __align__(16) float Bs[2][BK][BN];

    const int tid = threadIdx.x;
    const int bx = blockIdx.x, by = blockIdx.y;
    const int tx = tid & 15, ty = tid >> 4;

    u64 acc[8][4];
#pragma unroll
    for (int i = 0; i < 8; i++)
#pragma unroll
        for (int j = 0; j < 4; j++) acc[i][j] = 0ull;

    const int aRow = tid >> 1, aC = (tid & 1) * 8;
    const int at_t = tid >> 7, at_kk = (tid >> 3) & 15, at_b = (tid & 7) * 8;
    const int bRow = tid >> 4, bCol = (tid & 15) * 8;

    float4 A0, A1, B0, B1;

    auto loadT = [&](int k0) {
        if (!ATRANS) {
            const float* p = A + (size_t)(by * BM + aRow) * K + k0 + aC;
            A0 = *(const float4*)(p);
            A1 = *(const float4*)(p + 4);
        } else {
            const float* p = A + ((size_t)(by * 2 + at_t) * K + (k0 + at_kk)) * 64 + at_b;
            A0 = *(const float4*)(p);
            A1 = *(const float4*)(p + 4);
        }
        const float* pb = B + (size_t)(k0 + bRow) * N + bx * BN + bCol;
        B0 = *(const float4*)(pb);
        B1 = *(const float4*)(pb + 4);
    };
    auto storeT = [&](int buf) {
        if (!ATRANS) {
            As[buf][aC + 0][aRow] = A0.x; As[buf][aC + 1][aRow] = A0.y;
            As[buf][aC + 2][aRow] = A0.z; As[buf][aC + 3][aRow] = A0.w;
            As[buf][aC + 4][aRow] = A1.x; As[buf][aC + 5][aRow] = A1.y;
            As[buf][aC + 6][aRow] = A1.z; As[buf][aC + 7][aRow] = A1.w;
        } else {
            *(float4*)&As[buf][at_kk][at_t * 64 + at_b]     = A0;
            *(float4*)&As[buf][at_kk][at_t * 64 + at_b + 4] = A1;
        }
        *(float4*)&Bs[buf][bRow][bCol]     = B0;
        *(float4*)&Bs[buf][bRow][bCol + 4] = B1;
    };

    loadT(0);
    storeT(0);
    __syncthreads();

    const int nIter = K / BK;
    for (int it = 0; it < nIter; ++it) {
        const int cur = it & 1;
        if (it + 1 < nIter) loadT((it + 1) * BK);

#pragma unroll
        for (int kk = 0; kk < BK; kk++) {
            float4 alo = *(const float4*)&As[cur][kk][ty * 8];
            float4 ahi = *(const float4*)&As[cur][kk][ty * 8 + 4];
            ulonglong2 b01 = *(const ulonglong2*)&Bs[cur][kk][tx * 8];
            ulonglong2 b23 = *(const ulonglong2*)&Bs[cur][kk][tx * 8 + 4];
            float a[8] = {alo.x, alo.y, alo.z, alo.w, ahi.x, ahi.y, ahi.z, ahi.w};
#pragma unroll
            for (int i = 0; i < 8; i++) {
                u64 ad = pack2(a[i], a[i]);
                acc[i][0] = fma2(ad, b01.x, acc[i][0]);
                acc[i][1] = fma2(ad, b01.y, acc[i][1]);
                acc[i][2] = fma2(ad, b23.x, acc[i][2]);
                acc[i][3] = fma2(ad, b23.y, acc[i][3]);
            }
        }
        if (it + 1 < nIter) storeT(cur ^ 1);
        __syncthreads();
    }

    const int row0 = by * BM + ty * 8, col0 = bx * BN + tx * 8;
#pragma unroll
    for (int i = 0; i < 8; i++) {
        float out[8];
#pragma unroll
        for (int j = 0; j < 4; j++) {
            float2 f = unpack2(acc[i][j]);
            out[2 * j] = f.x; out[2 * j + 1] = f.y;
        }
#pragma unroll
        for (int j = 0; j < 8; j++) {
            float v = out[j] + bias[col0 + j];
            if (LEAKY) v = v >= 0.f ? v : 0.01f * v;
            out[j] = v;
        }
        *(float4*)&C[(size_t)(row0 + i) * N + col0]     = make_float4(out[0], out[1], out[2], out[3]);
        *(float4*)&C[(size_t)(row0 + i) * N + col0 + 4] = make_float4(out[4], out[5], out[6], out[7]);
    }
}

// ---------------------------------------------------------------------------
__global__ void transpose_h0(const float* __restrict__ in, float* __restrict__ out) {
    int i = blockIdx.x * 256 + threadIdx.x;        // 65536
    int c = i >> 6, r = i & 63;
    out[i] = in[(size_t)r * HID + c];              // out[c][r]
}
// Also resets the scan barrier counters for the next launch (stream-ordered).
__global__ void transpose_hfinal(const float* __restrict__ hsTlast, float* __restrict__ out) {
    int i = blockIdx.x * 256 + threadIdx.x;        // 65536
    int r = i >> 10, c = i & 1023;
    out[i] = hsTlast[(size_t)c * 64 + r];          // out[r][c]
    if (i < 4) g_cnt4[i * 32] = 0;
}

// ---------------------------------------------------------------------------
extern "C" void kernel_launch(void* const* d_in, const int* in_sizes, int n_in,
                              void* d_out, int out_size)
{
    const float* x   = (const float*)d_in[0];
    const float* h0  = (const float*)d_in[1];
    const float* i_h = (const float*)d_in[2];
    const float* h_h = (const float*)d_in[3];
    const float* h_o = (const float*)d_in[4];
    const float* b_i = (const float*)d_in[5];
    const float* b_o = (const float*)d_in[6];
    float* out = (float*)d_out;

    float *xi = nullptr, *hsT = nullptr, *h0T = nullptr;
    cudaGetSymbolAddress((void**)&xi,  g_xi);
    cudaGetSymbolAddress((void**)&hsT, g_hsT);
    cudaGetSymbolAddress((void**)&h0T, g_h0T);

    const int SCAN_SMEM = 131072 + 32768 + 16 * 288 * 8;   // 200704
    static int smem_set = 0;
    if (!smem_set) {
        cudaFuncSetAttribute(rnn_scan, cudaFuncAttributeMaxDynamicSharedMemorySize, SCAN_SMEM);
        smem_set = 1;
    }

    // launch #1: dummy (profiler captures launch #4 = rnn_scan)
    noop_k<<<1, 32>>>();

    // launch #2: transpose h0 -> [c][r]
    transpose_h0<<<256, 256>>>(h0, h0T);

    // launch #3: xi = x @ i_h + b_i : [32768,512]@[512,1024]
    {
        dim3 grid(HID / 128, (SEQL * BATCH) / 128);
        sgemm_db<false, false><<<grid, 256>>>(x, i_h, b_i, xi, SEQL * BATCH, HID, INF);
    }

    // launch #4: persistent scan (all 512 steps in one launch)
    rnn_scan<<<NBLK, SCAN_THREADS, SCAN_SMEM>>>(h0T, h_h, xi, hsT);

    // launch #5: outputs = leaky_relu(hsT @ h_o + b_o)
    {
        dim3 grid(OUTF / 128, (SEQL * BATCH) / 128);
        sgemm_db<true, true><<<grid, 256>>>(hsT, h_o, b_o, out, SEQL * BATCH, OUTF, HID);
    }

    // launch #6: h_final = transpose(hsT[511])  (+ barrier counter reset)
    transpose_hfinal<<<256, 256>>>(hsT + (size_t)(SEQL - 1) * BATCH * HID,
                                   out + (size_t)SEQL * BATCH * OUTF);
}

// round 15
// speedup vs baseline: 1.0264x; 1.0264x over previous
#include <cuda_runtime.h>
#include <math.h>

#define SEQL 512
#define BATCH 64
#define INF 512
#define HID 1024
#define OUTF 512
#define NBLK 128
#define SCAN_THREADS 512

typedef unsigned long long u64;

// Scratch (device globals; allocation-free)
__device__ float g_xi [(size_t)SEQL * BATCH * HID];   // [t][b][c] row-major
__device__ float g_hsT[(size_t)SEQL * BATCH * HID];   // [t][c][r] transposed
__device__ float g_h0T[(size_t)BATCH * HID];          // [c][r]
__device__ unsigned g_cnt4[128];                      // 4 counters, 32-word spaced

// ---------------- f32x2 helpers ----------------
__device__ __forceinline__ u64 pack2(float x, float y) {
    u64 d; asm("mov.b64 %0,{%1,%2};" : "=l"(d) : "f"(x), "f"(y)); return d;
}
__device__ __forceinline__ float2 unpack2(u64 d) {
    float2 v; asm("mov.b64 {%0,%1},%2;" : "=f"(v.x), "=f"(v.y) : "l"(d)); return v;
}
__device__ __forceinline__ u64 fma2(u64 a, u64 b, u64 c) {
    u64 d; asm("fma.rn.f32x2 %0,%1,%2,%3;" : "=l"(d) : "l"(a), "l"(b), "l"(c)); return d;
}
__device__ __forceinline__ u64 add2(u64 a, u64 b) {
    u64 d; asm("add.rn.f32x2 %0,%1,%2;" : "=l"(d) : "l"(a), "l"(b)); return d;
}

// fast tanh: 1 - 2/(e^{2x}+1). 2 MUFU + few FLOPs, rel err ~1e-6.
__device__ __forceinline__ float fast_tanh(float x) {
    float e = __expf(2.0f * x);
    return 1.0f - __fdividef(2.0f, e + 1.0f);
}

// Dummy first launch: keeps the profiler's capture window on rnn_scan (#4).
__global__ void noop_k() {}

// ---------------------------------------------------------------------------
// Persistent scan: h_t = tanh(xi_t + h_{t-1} @ W).
// 128 blocks = 32 colgroups(32 cols) x 4 rowgroups(16 rows); 512 threads.
// h staged via SMEM (one 32KB buffer, two 512-k phases). Phase-1's LDGs are
// issued into registers BEFORE phase-0's GEMM, so their latency hides under
// ~2000 cycles of FMA work. GEMM lane tile 8r x 2c (R13 proven mapping).
// W slice [1024][32] in SMEM as float2 (128KB). 16 warps = 16 k-splits.
// ---------------------------------------------------------------------------
__global__ void __launch_bounds__(SCAN_THREADS, 1) rnn_scan(
    const float* __restrict__ h0T, const float* __restrict__ W,
    const float* __restrict__ xi, float* __restrict__ hsT)
{
    extern __shared__ char smdyn[];
    float2* wS = (float2*)smdyn;                  // [1024][16] float2 = 128KB
    float*  hS = (float*)(smdyn + 131072);        // [512 k][16 r] = 32KB
    u64*  sRed = (u64*)(smdyn + 131072 + 32768);  // [16][32][9] u64 = 36864B

    const int tid = threadIdx.x;
    const int cgB = blockIdx.x >> 2;       // colgroup 0..31
    const int rgB = blockIdx.x & 3;        // rowgroup 0..3
    const int cb  = cgB * 32;
    const int rb  = rgB * 16;

    // Load W column slice once
    for (int i = tid; i < 1024 * 16; i += SCAN_THREADS) {
        int k = i >> 4, c2 = i & 15;
        wS[i] = make_float2(W[(size_t)k * HID + cb + 2 * c2],
                            W[(size_t)k * HID + cb + 2 * c2 + 1]);
    }

    const int q    = tid >> 5;             // k-split 0..15 (warp id)
    const int l    = tid & 31;
    const int qd   = l & 1;                // row half: rows qd*8..+8 of 16
    const int cgl  = l >> 1;               // col pair 0..15

    const int rrc = tid >> 3;              // reduce: local col 0..31
    const int rrp = tid & 7;               // reduce: row pair 0..7

    // staging roles: 4 float4 per thread per phase
    const int st_k0 = tid >> 2;            // base k (0..127), +128 per i
    const int st_rq = (tid & 3) * 4;       // row quad

    unsigned* cnt = &g_cnt4[rgB * 32];     // per-rowgroup barrier counter

    for (int t = 0; t < SEQL; ++t) {
        // ---- prefetch xi for epilogue (hidden under GEMM) ----
        float x0 = 0.f, x1 = 0.f;
        if (tid < 256) {
            const float* xit = xi + (size_t)t * BATCH * HID;
            x0 = __ldg(&xit[(size_t)(rb + 2 * rrp)     * HID + cb + rrc]);
            x1 = __ldg(&xit[(size_t)(rb + 2 * rrp + 1) * HID + cb + rrc]);
        }

        const float* hin = t ? hsT + (size_t)(t - 1) * BATCH * HID : h0T;

        // acc[cc*4+ro]: col cc (0,1), row-pair ro (0..3) of the 8 rows
        u64 acc[8];
#pragma unroll
        for (int i = 0; i < 8; ++i) acc[i] = 0ull;

        // ---- stage phase 0 (hS is free: end-of-step sync guarantees it) ----
        {
            const float* src = hin + rb;
#pragma unroll
            for (int i = 0; i < 4; ++i) {
                int kk = st_k0 + i * 128;
                float4 v = *(const float4*)(src + (size_t)kk * 64 + st_rq);
                *(float4*)&hS[kk * 16 + st_rq] = v;
            }
        }

        // ---- issue phase-1 LDGs now; latency hides under phase-0 GEMM ----
        float4 s1[4];
        {
            const float* src = hin + (size_t)512 * 64 + rb;
#pragma unroll
            for (int i = 0; i < 4; ++i) {
                int kk = st_k0 + i * 128;
                s1[i] = *(const float4*)(src + (size_t)kk * 64 + st_rq);
            }
        }
        __syncthreads();

        // ---- GEMM phase 0 ----
        {
            const float*  hp = hS + (q * 32) * 16 + qd * 8;
            const float2* wp = wS + (size_t)(q * 32) * 16 + cgl;
#pragma unroll 8
            for (int k = 0; k < 32; ++k) {
                ulonglong2 hlo = *(const ulonglong2*)(hp + k * 16);
                ulonglong2 hhi = *(const ulonglong2*)(hp + k * 16 + 4);
                float2 w2 = wp[(size_t)k * 16];
                u64 wx = pack2(w2.x, w2.x);
                u64 wy = pack2(w2.y, w2.y);
                acc[0] = fma2(hlo.x, wx, acc[0]);
                acc[1] = fma2(hlo.y, wx, acc[1]);
                acc[2] = fma2(hhi.x, wx, acc[2]);
                acc[3] = fma2(hhi.y, wx, acc[3]);
                acc[4] = fma2(hlo.x, wy, acc[4]);
                acc[5] = fma2(hlo.y, wy, acc[5]);
                acc[6] = fma2(hhi.x, wy, acc[6]);
                acc[7] = fma2(hhi.y, wy, acc[7]);
            }
        }
        __syncthreads();

        // ---- store phase-1 stage (regs already loaded) ----
        {
#pragma unroll
            for (int i = 0; i < 4; ++i) {
                int kk = st_k0 + i * 128;
                *(float4*)&hS[kk * 16 + st_rq] = s1[i];
            }
        }
        __syncthreads();

        // ---- GEMM phase 1 ----
        {
            const float*  hp = hS + (q * 32) * 16 + qd * 8;
            const float2* wp = wS + (size_t)(512 + q * 32) * 16 + cgl;
#pragma unroll 8
            for (int k = 0; k < 32; ++k) {
                ulonglong2 hlo = *(const ulonglong2*)(hp + k * 16);
                ulonglong2 hhi = *(const ulonglong2*)(hp + k * 16 + 4);
                float2 w2 = wp[(size_t)k * 16];
                u64 wx = pack2(w2.x, w2.x);
                u64 wy = pack2(w2.y, w2.y);
                acc[0] = fma2(hlo.x, wx, acc[0]);
                acc[1] = fma2(hlo.y, wx, acc[1]);
                acc[2] = fma2(hhi.x, wx, acc[2]);
                acc[3] = fma2(hhi.y, wx, acc[3]);
                acc[4] = fma2(hlo.x, wy, acc[4]);
                acc[5] = fma2(hlo.y, wy, acc[5]);
                acc[6] = fma2(hhi.x, wy, acc[6]);
                acc[7] = fma2(hhi.y, wy, acc[7]);
            }
        }

        // ---- partial store: sRed[q][2cgl+cc][qd*4+ro] (rp padded to 9) ----
        {
            u64* base = sRed + (size_t)q * 288;   // 32*9
#pragma unroll
            for (int cc = 0; cc < 2; ++cc)
#pragma unroll
                for (int ro = 0; ro < 4; ++ro)
                    base[(size_t)(2 * cgl + cc) * 9 + (qd * 4 + ro)] = acc[cc * 4 + ro];
        }
        __syncthreads();

        // ---- 16-way reduce + tanh + store h_t (256 threads, 1 u64 each) ----
        if (tid < 256) {
            u64 s = sRed[(size_t)rrc * 9 + rrp];
#pragma unroll
            for (int qq = 1; qq < 16; ++qq)
                s = add2(s, sRed[(size_t)qq * 288 + (size_t)rrc * 9 + rrp]);
            float2 f = unpack2(s);
            float v0 = fast_tanh(f.x + x0);
            float v1 = fast_tanh(f.y + x1);
            *(u64*)(hsT + (size_t)t * BATCH * HID + (size_t)(cb + rrc) * 64 + rb + 2 * rrp)
                = pack2(v0, v1);
        }

        // ---- rowgroup barrier (32 blocks): release-inc + poll counter ----
        __syncthreads();
        if (tid == 0) {
            asm volatile("red.release.gpu.global.add.u32 [%0], 1;"
                         :: "l"(cnt) : "memory");
        }
        if (tid < 32) {
            const unsigned target = 32u * (unsigned)(t + 1);
            unsigned cur;
            do {
                asm volatile("ld.acquire.gpu.u32 %0,[%1];"
                             : "=r"(cur) : "l"(cnt) : "memory");
            } while (cur < target);
        }
        __syncthreads();
    }
}

// ---------------------------------------------------------------------------
// Double-buffered 128x128x16 f32x2 GEMM: C = A @ B + bias, optional leaky.
// ATRANS: A stored as [M/64][K][64] (transposed hidden-state history).
// ---------------------------------------------------------------------------
template <bool ATRANS, bool LEAKY>
__global__ __launch_bounds__(256) void sgemm_db(
    const float* __restrict__ A, const float* __restrict__ B,
    const float* __restrict__ bias, float* __restrict__ C,
    int M, int N, int K)
{
    constexpr int BM = 128, BN = 128, BK = 16;
    __shared__ __align__(16) float As[2][BK][BM];
    __shared__ __align__(16) float Bs[2][BK][BN];

    const int tid = threadIdx.x;
    const int bx = blockIdx.x, by = blockIdx.y;
    const int tx = tid & 15, ty = tid >> 4;

    u64 acc[8][4];
#pragma unroll
    for (int i = 0; i < 8; i++)
#pragma unroll
        for (int j = 0; j < 4; j++) acc[i][j] = 0ull;

    const int aRow = tid >> 1, aC = (tid & 1) * 8;
    const int at_t = tid >> 7, at_kk = (tid >> 3) & 15, at_b = (tid & 7) * 8;
    const int bRow = tid >> 4, bCol = (tid & 15) * 8;

    float4 A0, A1, B0, B1;

    auto loadT = [&](int k0) {
        if (!ATRANS) {
            const float* p = A + (size_t)(by * BM + aRow) * K + k0 + aC;
            A0 = *(const float4*)(p);
            A1 = *(const float4*)(p + 4);
        } else {
            const float* p = A + ((size_t)(by * 2 + at_t) * K + (k0 + at_kk)) * 64 + at_b;
            A0 = *(const float4*)(p);
            A1 = *(const float4*)(p + 4);
        }
        const float* pb = B + (size_t)(k0 + bRow) * N + bx * BN + bCol;
        B0 = *(const float4*)(pb);
        B1 = *(const float4*)(pb + 4);
    };
    auto storeT = [&](int buf) {
        if (!ATRANS) {
            As[buf][aC + 0][aRow] = A0.x; As[buf][aC + 1][aRow] = A0.y;
            As[buf][aC + 2][aRow] = A0.z; As[buf][aC + 3][aRow] = A0.w;
            As[buf][aC + 4][aRow] = A1.x; As[buf][aC + 5][aRow] = A1.y;
            As[buf][aC + 6][aRow] = A1.z; As[buf][aC + 7][aRow] = A1.w;
        } else {
            *(float4*)&As[buf][at_kk][at_t * 64 + at_b]     = A0;
            *(float4*)&As[buf][at_kk][at_t * 64 + at_b + 4] = A1;
        }
        *(float4*)&Bs[buf][bRow][bCol]     = B0;
        *(float4*)&Bs[buf][bRow][bCol + 4] = B1;
    };

    loadT(0);
    storeT(0);
    __syncthreads();

    const int nIter = K / BK;
    for (int it = 0; it < nIter; ++it) {
        const int cur = it & 1;
        if (it + 1 < nIter) loadT((it + 1) * BK);

#pragma unroll
        for (int kk = 0; kk < BK; kk++) {
            float4 alo = *(const float4*)&As[cur][kk][ty * 8];
            float4 ahi = *(const float4*)&As[cur][kk][ty * 8 + 4];
            ulonglong2 b01 = *(const ulonglong2*)&Bs[cur][kk][tx * 8];
            ulonglong2 b23 = *(const ulonglong2*)&Bs[cur][kk][tx * 8 + 4];
            float a[8] = {alo.x, alo.y, alo.z, alo.w, ahi.x, ahi.y, ahi.z, ahi.w};
#pragma unroll
            for (int i = 0; i < 8; i++) {
                u64 ad = pack2(a[i], a[i]);
                acc[i][0] = fma2(ad, b01.x, acc[i][0]);
                acc[i][1] = fma2(ad, b01.y, acc[i][1]);
                acc[i][2] = fma2(ad, b23.x, acc[i][2]);
                acc[i][3] = fma2(ad, b23.y, acc[i][3]);
            }
        }
        if (it + 1 < nIter) storeT(cur ^ 1);
        __syncthreads();
    }

    const int row0 = by * BM + ty * 8, col0 = bx * BN + tx * 8;
#pragma unroll
    for (int i = 0; i < 8; i++) {
        float out[8];
#pragma unroll
        for (int j = 0; j < 4; j++) {
            float2 f = unpack2(acc[i][j]);
            out[2 * j] = f.x; out[2 * j + 1] = f.y;
        }
#pragma unroll
        for (int j = 0; j < 8; j++) {
            float v = out[j] + bias[col0 + j];
            if (LEAKY) v = v >= 0.f ? v : 0.01f * v;
            out[j] = v;
        }
        *(float4*)&C[(size_t)(row0 + i) * N + col0]     = make_float4(out[0], out[1], out[2], out[3]);
        *(float4*)&C[(size_t)(row0 + i) * N + col0 + 4] = make_float4(out[4], out[5], out[6], out[7]);
    }
}

// ---------------------------------------------------------------------------
__global__ void transpose_h0(const float* __restrict__ in, float* __restrict__ out) {
    int i = blockIdx.x * 256 + threadIdx.x;        // 65536
    int c = i >> 6, r = i & 63;
    out[i] = in[(size_t)r * HID + c];              // out[c][r]
}
// Also resets the scan barrier counters for the next launch (stream-ordered).
__global__ void transpose_hfinal(const float* __restrict__ hsTlast, float* __restrict__ out) {
    int i = blockIdx.x * 256 + threadIdx.x;        // 65536
    int r = i >> 10, c = i & 1023;
    out[i] = hsTlast[(size_t)c * 64 + r];          // out[r][c]
    if (i < 4) g_cnt4[i * 32] = 0;
}

// ---------------------------------------------------------------------------
extern "C" void kernel_launch(void* const* d_in, const int* in_sizes, int n_in,
                              void* d_out, int out_size)
{
    const float* x   = (const float*)d_in[0];
    const float* h0  = (const float*)d_in[1];
    const float* i_h = (const float*)d_in[2];
    const float* h_h = (const float*)d_in[3];
    const float* h_o = (const float*)d_in[4];
    const float* b_i = (const float*)d_in[5];
    const float* b_o = (const float*)d_in[6];
    float* out = (float*)d_out;

    float *xi = nullptr, *hsT = nullptr, *h0T = nullptr;
    cudaGetSymbolAddress((void**)&xi,  g_xi);
    cudaGetSymbolAddress((void**)&hsT, g_hsT);
    cudaGetSymbolAddress((void**)&h0T, g_h0T);

    const int SCAN_SMEM = 131072 + 32768 + 16 * 288 * 8;   // 200704
    static int smem_set = 0;
    if (!smem_set) {
        cudaFuncSetAttribute(rnn_scan, cudaFuncAttributeMaxDynamicSharedMemorySize, SCAN_SMEM);
        smem_set = 1;
    }

    // launch #1: dummy (profiler captures launch #4 = rnn_scan)
    noop_k<<<1, 32>>>();

    // launch #2: transpose h0 -> [c][r]
    transpose_h0<<<256, 256>>>(h0, h0T);

    // launch #3: xi = x @ i_h + b_i : [32768,512]@[512,1024]
    {
        dim3 grid(HID / 128, (SEQL * BATCH) / 128);
        sgemm_db<false, false><<<grid, 256>>>(x, i_h, b_i, xi, SEQL * BATCH, HID, INF);
    }

    // launch #4: persistent scan (all 512 steps in one launch)
    rnn_scan<<<NBLK, SCAN_THREADS, SCAN_SMEM>>>(h0T, h_h, xi, hsT);

    // launch #5: outputs = leaky_relu(hsT @ h_o + b_o)
    {
        dim3 grid(OUTF / 128, (SEQL * BATCH) / 128);
        sgemm_db<true, true><<<grid, 256>>>(hsT, h_o, b_o, out, SEQL * BATCH, OUTF, HID);
    }

    // launch #6: h_final = transpose(hsT[511])  (+ barrier counter reset)
    transpose_hfinal<<<256, 256>>>(hsT + (size_t)(SEQL - 1) * BATCH * HID,
                                   out + (size_t)SEQL * BATCH * OUTF);
}

// round 17
// speedup vs baseline: 1.0350x; 1.0084x over previous
#include <cuda_runtime.h>
#include <cstdint>
#include <math.h>

#define SEQL 512
#define BATCH 64
#define INF 512
#define HID 1024
#define OUTF 512
#define NBLK 128
#define SCAN_THREADS 512

typedef unsigned long long u64;

// Scratch (device globals; allocation-free)
__device__ float g_xi [(size_t)SEQL * BATCH * HID];   // [t][b][c] row-major
__device__ float g_hsT[(size_t)SEQL * BATCH * HID];   // [t][c][r] transposed
__device__ float g_h0T[(size_t)BATCH * HID];          // [c][r]
__device__ unsigned g_cnt4[128];                      // 4 counters, 32-word spaced

// ---------------- f32x2 helpers ----------------
__device__ __forceinline__ u64 pack2(float x, float y) {
    u64 d; asm("mov.b64 %0,{%1,%2};" : "=l"(d) : "f"(x), "f"(y)); return d;
}
__device__ __forceinline__ float2 unpack2(u64 d) {
    float2 v; asm("mov.b64 {%0,%1},%2;" : "=f"(v.x), "=f"(v.y) : "l"(d)); return v;
}
__device__ __forceinline__ u64 fma2(u64 a, u64 b, u64 c) {
    u64 d; asm("fma.rn.f32x2 %0,%1,%2,%3;" : "=l"(d) : "l"(a), "l"(b), "l"(c)); return d;
}
__device__ __forceinline__ u64 add2(u64 a, u64 b) {
    u64 d; asm("add.rn.f32x2 %0,%1,%2;" : "=l"(d) : "l"(a), "l"(b)); return d;
}

// fast tanh: 1 - 2/(e^{2x}+1). 2 MUFU + few FLOPs, rel err ~1e-6.
__device__ __forceinline__ float fast_tanh(float x) {
    float e = __expf(2.0f * x);
    return 1.0f - __fdividef(2.0f, e + 1.0f);
}

__device__ __forceinline__ void cp_async16(unsigned int smem_addr, const void* gptr) {
    asm volatile("cp.async.ca.shared.global [%0], [%1], 16;"
                 :: "r"(smem_addr), "l"(gptr));
}
__device__ __forceinline__ void cp_commit() {
    asm volatile("cp.async.commit_group;");
}
template <int N>
__device__ __forceinline__ void cp_wait() {
    asm volatile("cp.async.wait_group %0;" :: "n"(N));
}

// ---------------------------------------------------------------------------
// Persistent scan (R15 best version, unchanged): h_t = tanh(xi_t + h @ W).
// ---------------------------------------------------------------------------
__global__ void __launch_bounds__(SCAN_THREADS, 1) rnn_scan(
    const float* __restrict__ h0T, const float* __restrict__ W,
    const float* __restrict__ xi, float* __restrict__ hsT)
{
    extern __shared__ char smdyn[];
    float2* wS = (float2*)smdyn;                  // [1024][16] float2 = 128KB
    float*  hS = (float*)(smdyn + 131072);        // [512 k][16 r] = 32KB
    u64*  sRed = (u64*)(smdyn + 131072 + 32768);  // [16][32][9] u64 = 36864B

    const int tid = threadIdx.x;
    const int cgB = blockIdx.x >> 2;
    const int rgB = blockIdx.x & 3;
    const int cb  = cgB * 32;
    const int rb  = rgB * 16;

    for (int i = tid; i < 1024 * 16; i += SCAN_THREADS) {
        int k = i >> 4, c2 = i & 15;
        wS[i] = make_float2(W[(size_t)k * HID + cb + 2 * c2],
                            W[(size_t)k * HID + cb + 2 * c2 + 1]);
    }

    const int q    = tid >> 5;
    const int l    = tid & 31;
    const int qd   = l & 1;
    const int cgl  = l >> 1;

    const int rrc = tid >> 3;
    const int rrp = tid & 7;

    const int st_k0 = tid >> 2;
    const int st_rq = (tid & 3) * 4;

    unsigned* cnt = &g_cnt4[rgB * 32];

    for (int t = 0; t < SEQL; ++t) {
        float x0 = 0.f, x1 = 0.f;
        if (tid < 256) {
            const float* xit = xi + (size_t)t * BATCH * HID;
            x0 = __ldg(&xit[(size_t)(rb + 2 * rrp)     * HID + cb + rrc]);
            x1 = __ldg(&xit[(size_t)(rb + 2 * rrp + 1) * HID + cb + rrc]);
        }

        const float* hin = t ? hsT + (size_t)(t - 1) * BATCH * HID : h0T;

        u64 acc[8];
#pragma unroll
        for (int i = 0; i < 8; ++i) acc[i] = 0ull;

        {
            const float* src = hin + rb;
#pragma unroll
            for (int i = 0; i < 4; ++i) {
                int kk = st_k0 + i * 128;
                float4 v = *(const float4*)(src + (size_t)kk * 64 + st_rq);
                *(float4*)&hS[kk * 16 + st_rq] = v;
            }
        }

        float4 s1[4];
        {
            const float* src = hin + (size_t)512 * 64 + rb;
#pragma unroll
            for (int i = 0; i < 4; ++i) {
                int kk = st_k0 + i * 128;
                s1[i] = *(const float4*)(src + (size_t)kk * 64 + st_rq);
            }
        }
        __syncthreads();

        {
            const float*  hp = hS + (q * 32) * 16 + qd * 8;
            const float2* wp = wS + (size_t)(q * 32) * 16 + cgl;
#pragma unroll 8
            for (int k = 0; k < 32; ++k) {
                ulonglong2 hlo = *(const ulonglong2*)(hp + k * 16);
                ulonglong2 hhi = *(const ulonglong2*)(hp + k * 16 + 4);
                float2 w2 = wp[(size_t)k * 16];
                u64 wx = pack2(w2.x, w2.x);
                u64 wy = pack2(w2.y, w2.y);
                acc[0] = fma2(hlo.x, wx, acc[0]);
                acc[1] = fma2(hlo.y, wx, acc[1]);
                acc[2] = fma2(hhi.x, wx, acc[2]);
                acc[3] = fma2(hhi.y, wx, acc[3]);
                acc[4] = fma2(hlo.x, wy, acc[4]);
                acc[5] = fma2(hlo.y, wy, acc[5]);
                acc[6] = fma2(hhi.x, wy, acc[6]);
                acc[7] = fma2(hhi.y, wy, acc[7]);
            }
        }
        __syncthreads();

        {
#pragma unroll
            for (int i = 0; i < 4; ++i) {
                int kk = st_k0 + i * 128;
                *(float4*)&hS[kk * 16 + st_rq] = s1[i];
            }
        }
        __syncthreads();

        {
            const float*  hp = hS + (q * 32) * 16 + qd * 8;
            const float2* wp = wS + (size_t)(512 + q * 32) * 16 + cgl;
#pragma unroll 8
            for (int k = 0; k < 32; ++k) {
                ulonglong2 hlo = *(const ulonglong2*)(hp + k * 16);
                ulonglong2 hhi = *(const ulonglong2*)(hp + k * 16 + 4);
                float2 w2 = wp[(size_t)k * 16];
                u64 wx = pack2(w2.x, w2.x);
                u64 wy = pack2(w2.y, w2.y);
                acc[0] = fma2(hlo.x, wx, acc[0]);
                acc[1] = fma2(hlo.y, wx, acc[1]);
                acc[2] = fma2(hhi.x, wx, acc[2]);
                acc[3] = fma2(hhi.y, wx, acc[3]);
                acc[4] = fma2(hlo.x, wy, acc[4]);
                acc[5] = fma2(hlo.y, wy, acc[5]);
                acc[6] = fma2(hhi.x, wy, acc[6]);
                acc[7] = fma2(hhi.y, wy, acc[7]);
            }
        }

        {
            u64* base = sRed + (size_t)q * 288;
#pragma unroll
            for (int cc = 0; cc < 2; ++cc)
#pragma unroll
                for (int ro = 0; ro < 4; ++ro)
                    base[(size_t)(2 * cgl + cc) * 9 + (qd * 4 + ro)] = acc[cc * 4 + ro];
        }
        __syncthreads();

        if (tid < 256) {
            u64 s = sRed[(size_t)rrc * 9 + rrp];
#pragma unroll
            for (int qq = 1; qq < 16; ++qq)
                s = add2(s, sRed[(size_t)qq * 288 + (size_t)rrc * 9 + rrp]);
            float2 f = unpack2(s);
            float v0 = fast_tanh(f.x + x0);
            float v1 = fast_tanh(f.y + x1);
            *(u64*)(hsT + (size_t)t * BATCH * HID + (size_t)(cb + rrc) * 64 + rb + 2 * rrp)
                = pack2(v0, v1);
        }

        __syncthreads();
        if (tid == 0) {
            asm volatile("red.release.gpu.global.add.u32 [%0], 1;"
                         :: "l"(cnt) : "memory");
        }
        if (tid < 32) {
            const unsigned target = 32u * (unsigned)(t + 1);
            unsigned cur;
            do {
                asm volatile("ld.acquire.gpu.u32 %0,[%1];"
                             : "=r"(cur) : "l"(cnt) : "memory");
            } while (cur < target);
        }
        __syncthreads();
    }
}

// ---------------------------------------------------------------------------
// xi-GEMM: proven register-staged double-buffered kernel (unchanged).
// ---------------------------------------------------------------------------
template <bool LEAKY>
__global__ __launch_bounds__(256) void sgemm_db(
    const float* __restrict__ A, const float* __restrict__ B,
    const float* __restrict__ bias, float* __restrict__ C,
    int M, int N, int K)
{
    constexpr int BM = 128, BN = 128, BK = 16;
    __shared__ __align__(16) float As[2][BK][BM];
    __shared__ __align__(16) float Bs[2][BK][BN];

    const int tid = threadIdx.x;
    const int bx = blockIdx.x, by = blockIdx.y;
    const int tx = tid & 15, ty = tid >> 4;

    u64 acc[8][4];
#pragma unroll
    for (int i = 0; i < 8; i++)
#pragma unroll
        for (int j = 0; j < 4; j++) acc[i][j] = 0ull;

    const int aRow = tid >> 1, aC = (tid & 1) * 8;
    const int bRow = tid >> 4, bCol = (tid & 15) * 8;

    float4 A0, A1, B0, B1;

    auto loadT = [&](int k0) {
        const float* p = A + (size_t)(by * BM + aRow) * K + k0 + aC;
        A0 = *(const float4*)(p);
        A1 = *(const float4*)(p + 4);
        const float* pb = B + (size_t)(k0 + bRow) * N + bx * BN + bCol;
        B0 = *(const float4*)(pb);
        B1 = *(const float4*)(pb + 4);
    };
    auto storeT = [&](int buf) {
        As[buf][aC + 0][aRow] = A0.x; As[buf][aC + 1][aRow] = A0.y;
        As[buf][aC + 2][aRow] = A0.z; As[buf][aC + 3][aRow] = A0.w;
        As[buf][aC + 4][aRow] = A1.x; As[buf][aC + 5][aRow] = A1.y;
        As[buf][aC + 6][aRow] = A1.z; As[buf][aC + 7][aRow] = A1.w;
        *(float4*)&Bs[buf][bRow][bCol]     = B0;
        *(float4*)&Bs[buf][bRow][bCol + 4] = B1;
    };

    loadT(0);
    storeT(0);
    __syncthreads();

    const int nIter = K / BK;
    for (int it = 0; it < nIter; ++it) {
        const int cur = it & 1;
        if (it + 1 < nIter) loadT((it + 1) * BK);

#pragma unroll
        for (int kk = 0; kk < BK; kk++) {
            float4 alo = *(const float4*)&As[cur][kk][ty * 8];
            float4 ahi = *(const float4*)&As[cur][kk][ty * 8 + 4];
            ulonglong2 b01 = *(const ulonglong2*)&Bs[cur][kk][tx * 8];
            ulonglong2 b23 = *(const ulonglong2*)&Bs[cur][kk][tx * 8 + 4];
            float a[8] = {alo.x, alo.y, alo.z, alo.w, ahi.x, ahi.y, ahi.z, ahi.w};
#pragma unroll
            for (int i = 0; i < 8; i++) {
                u64 ad = pack2(a[i], a[i]);
                acc[i][0] = fma2(ad, b01.x, acc[i][0]);
                acc[i][1] = fma2(ad, b01.y, acc[i][1]);
                acc[i][2] = fma2(ad, b23.x, acc[i][2]);
                acc[i][3] = fma2(ad, b23.y, acc[i][3]);
            }
        }
        if (it + 1 < nIter) storeT(cur ^ 1);
        __syncthreads();
    }

    const int row0 = by * BM + ty * 8, col0 = bx * BN + tx * 8;
#pragma unroll
    for (int i = 0; i < 8; i++) {
        float out[8];
#pragma unroll
        for (int j = 0; j < 4; j++) {
            float2 f = unpack2(acc[i][j]);
            out[2 * j] = f.x; out[2 * j + 1] = f.y;
        }
#pragma unroll
        for (int j = 0; j < 8; j++) {
            float v = out[j] + bias[col0 + j];
            if (LEAKY) v = v >= 0.f ? v : 0.01f * v;
            out[j] = v;
        }
        *(float4*)&C[(size_t)(row0 + i) * N + col0]     = make_float4(out[0], out[1], out[2], out[3]);
        *(float4*)&C[(size_t)(row0 + i) * N + col0 + 4] = make_float4(out[4], out[5], out[6], out[7]);
    }
}

// ---------------------------------------------------------------------------
// out-GEMM: 4-stage cp.async pipeline. A = hsT chunked [M/64][K][64] (both A
// and B stream global->smem with no register staging). Leaky epilogue.
// ---------------------------------------------------------------------------
__global__ __launch_bounds__(256) void sgemm_ca(
    const float* __restrict__ A, const float* __restrict__ B,
    const float* __restrict__ bias, float* __restrict__ C,
    int M, int N, int K)
{
    constexpr int BM = 128, BN = 128, BK = 16, ST = 4;
    extern __shared__ float sca[];
    float* AsF = sca;                        // [ST][BK][BM] = 32KB
    float* BsF = sca + ST * BK * BM;         // [ST][BK][BN] = 32KB

    const int tid = threadIdx.x;
    const int bx = blockIdx.x, by = blockIdx.y;
    const int tx = tid & 15, ty = tid >> 4;

    u64 acc[8][4];
#pragma unroll
    for (int i = 0; i < 8; i++)
#pragma unroll
        for (int j = 0; j < 4; j++) acc[i][j] = 0ull;

    const unsigned int asBase = (unsigned int)__cvta_generic_to_shared(AsF);
    const unsigned int bsBase = (unsigned int)__cvta_generic_to_shared(BsF);

    auto issue_stage = [&](int s, int k0) {
#pragma unroll
        for (int j = 0; j < 2; ++j) {
            int idx = tid * 2 + j;
            int kk  = idx >> 5;
            int e4  = (idx & 31) * 4;
            // A: chunked [M/64][K][64]
            int chunk = by * 2 + (e4 >> 6);
            const float* ga = A + ((size_t)chunk * K + (k0 + kk)) * 64 + (e4 & 63);
            cp_async16(asBase + (unsigned int)(((s * BK + kk) * BM + e4) * 4), ga);
            // B: row-major [K][N]
            const float* gb = B + (size_t)(k0 + kk) * N + bx * BN + e4;
            cp_async16(bsBase + (unsigned int)(((s * BK + kk) * BN + e4) * 4), gb);
        }
        cp_commit();
    };

    const int nIter = K / BK;
    issue_stage(0, 0);
    if (nIter > 1) issue_stage(1, BK);
    if (nIter > 2) issue_stage(2, 2 * BK);

    for (int it = 0; it < nIter; ++it) {
        cp_wait<2>();          // stage `it` complete
        __syncthreads();       // visible to all; prev compute done
        if (it + 3 < nIter) issue_stage((it + 3) & 3, (it + 3) * BK);

        const int s = it & 3;
        const float* As = AsF + (size_t)s * BK * BM;
        const float* Bs = BsF + (size_t)s * BK * BN;
#pragma unroll
        for (int kk = 0; kk < BK; kk++) {
            float4 alo = *(const float4*)&As[kk * BM + ty * 8];
            float4 ahi = *(const float4*)&As[kk * BM + ty * 8 + 4];
            ulonglong2 b01 = *(const ulonglong2*)&Bs[kk * BN + tx * 8];
            ulonglong2 b23 = *(const ulonglong2*)&Bs[kk * BN + tx * 8 + 4];
            float a[8] = {alo.x, alo.y, alo.z, alo.w, ahi.x, ahi.y, ahi.z, ahi.w};
#pragma unroll
            for (int i = 0; i < 8; i++) {
                u64 ad = pack2(a[i], a[i]);
                acc[i][0] = fma2(ad, b01.x, acc[i][0]);
                acc[i][1] = fma2(ad, b01.y, acc[i][1]);
                acc[i][2] = fma2(ad, b23.x, acc[i][2]);
                acc[i][3] = fma2(ad, b23.y, acc[i][3]);
            }
        }
    }

    const int row0 = by * BM + ty * 8, col0 = bx * BN + tx * 8;
#pragma unroll
    for (int i = 0; i < 8; i++) {
        float out[8];
#pragma unroll
        for (int j = 0; j < 4; j++) {
            float2 f = unpack2(acc[i][j]);
            out[2 * j] = f.x; out[2 * j + 1] = f.y;
        }
#pragma unroll
        for (int j = 0; j < 8; j++) {
            float v = out[j] + bias[col0 + j];
            v = v >= 0.f ? v : 0.01f * v;
            out[j] = v;
        }
        *(float4*)&C[(size_t)(row0 + i) * N + col0]     = make_float4(out[0], out[1], out[2], out[3]);
        *(float4*)&C[(size_t)(row0 + i) * N + col0 + 4] = make_float4(out[4], out[5], out[6], out[7]);
    }
}

// ---------------------------------------------------------------------------
__global__ void transpose_h0(const float* __restrict__ in, float* __restrict__ out) {
    int i = blockIdx.x * 256 + threadIdx.x;        // 65536
    int c = i >> 6, r = i & 63;
    out[i] = in[(size_t)r * HID + c];              // out[c][r]
}
__global__ void transpose_hfinal(const float* __restrict__ hsTlast, float* __restrict__ out) {
    int i = blockIdx.x * 256 + threadIdx.x;        // 65536
    int r = i >> 10, c = i & 1023;
    out[i] = hsTlast[(size_t)c * 64 + r];          // out[r][c]
    if (i < 4) g_cnt4[i * 32] = 0;
}

// ---------------------------------------------------------------------------
extern "C" void kernel_launch(void* const* d_in, const int* in_sizes, int n_in,
                              void* d_out, int out_size)
{
    const float* x   = (const float*)d_in[0];
    const float* h0  = (const float*)d_in[1];
    const float* i_h = (const float*)d_in[2];
    const float* h_h = (const float*)d_in[3];
    const float* h_o = (const float*)d_in[4];
    const float* b_i = (const float*)d_in[5];
    const float* b_o = (const float*)d_in[6];
    float* out = (float*)d_out;

    float *xi = nullptr, *hsT = nullptr, *h0T = nullptr;
    cudaGetSymbolAddress((void**)&xi,  g_xi);
    cudaGetSymbolAddress((void**)&hsT, g_hsT);
    cudaGetSymbolAddress((void**)&h0T, g_h0T);

    const int SCAN_SMEM = 131072 + 32768 + 16 * 288 * 8;   // 200704
    const int CA_SMEM   = 65536;
    static int smem_set = 0;
    if (!smem_set) {
        cudaFuncSetAttribute(rnn_scan, cudaFuncAttributeMaxDynamicSharedMemorySize, SCAN_SMEM);
        cudaFuncSetAttribute(sgemm_ca, cudaFuncAttributeMaxDynamicSharedMemorySize, CA_SMEM);
        smem_set = 1;
    }

    // #1: transpose h0 -> [c][r]
    transpose_h0<<<256, 256>>>(h0, h0T);

    // #2: xi = x @ i_h + b_i : [32768,512]@[512,1024]
    {
        dim3 grid(HID / 128, (SEQL * BATCH) / 128);
        sgemm_db<false><<<grid, 256>>>(x, i_h, b_i, xi, SEQL * BATCH, HID, INF);
    }

    // #3: persistent scan (all 512 steps in one launch)
    rnn_scan<<<NBLK, SCAN_THREADS, SCAN_SMEM>>>(h0T, h_h, xi, hsT);

    // #4: outputs = leaky_relu(hsT @ h_o + b_o)  [cp.async pipeline; profiled]
    {
        dim3 grid(OUTF / 128, (SEQL * BATCH) / 128);
        sgemm_ca<<<grid, 256, CA_SMEM>>>(hsT, h_o, b_o, out, SEQL * BATCH, OUTF, HID);
    }

    // #5: h_final = transpose(hsT[511])  (+ barrier counter reset)
    transpose_hfinal<<<256, 256>>>(hsT + (size_t)(SEQL - 1) * BATCH * HID,
                                   out + (size_t)SEQL * BATCH * OUTF);
}